// round 14
// baseline (speedup 1.0000x reference)
#include <cuda_runtime.h>
#include <cuda_fp16.h>
#include <math.h>

#define B_  4
#define S_  2048
#define D_  1024
#define H_  16
#define HD_ 64
#define M_  (B_*S_)

// Q scale: 1/8 (=HD^-0.5) times log2(e), so softmax can use raw ex2.
#define QSCALE 0.18033688011112042f

// Scratch (allocation-free rule: __device__ globals)
__device__ __half g_xh[M_*D_];         // half input x
__device__ __half g_wqh[D_*D_];
__device__ __half g_wkh[D_*D_];
__device__ __half g_wvh[D_*D_];
__device__ __half g_woh[D_*D_];
__device__ __half g_prv[M_*D_];        // V projection (half)
__device__ __half g_qh[M_*D_];         // rotary'd Q x QSCALE
__device__ __half g_kh[M_*D_];         // rotary'd K
__device__ __half g_vt[M_*D_];         // V transposed: [B*H][64][2048]
__device__ __half g_cth[M_*D_];        // attention output (half)

extern __shared__ float dynsm[];

__device__ __forceinline__ void mma_f16(float* c,
                                        unsigned a0, unsigned a1, unsigned a2, unsigned a3,
                                        unsigned b0, unsigned b1)
{
    asm volatile(
        "mma.sync.aligned.m16n8k16.row.col.f32.f16.f16.f32 "
        "{%0,%1,%2,%3}, {%4,%5,%6,%7}, {%8,%9}, {%0,%1,%2,%3};"
        : "+f"(c[0]), "+f"(c[1]), "+f"(c[2]), "+f"(c[3])
        : "r"(a0), "r"(a1), "r"(a2), "r"(a3), "r"(b0), "r"(b1));
}

__device__ __forceinline__ void cpa16(unsigned saddr, const void* gptr) {
    asm volatile("cp.async.cg.shared.global [%0], [%1], 16;" :: "r"(saddr), "l"(gptr));
}
#define CP_COMMIT() asm volatile("cp.async.commit_group;")
#define CP_WAIT0()  asm volatile("cp.async.wait_group 0;")

__device__ __forceinline__ unsigned ldh2(const __half* p) {
    return *(const unsigned*)p;
}
__device__ __forceinline__ float ex2f(float x) {
    float y;
    asm("ex2.approx.f32 %0, %1;" : "=f"(y) : "f"(x));
    return y;
}

// ---------------------------------------------------------------------------
// fp32 -> half conversions
// ---------------------------------------------------------------------------
__global__ __launch_bounds__(256) void f2h_kernel(const float* __restrict__ in,
                                                  __half* __restrict__ out, int n4)
{
    int i = blockIdx.x * blockDim.x + threadIdx.x;
    if (i < n4) {
        float4 v = ((const float4*)in)[i];
        ((__half2*)out)[2*i]     = __floats2half2_rn(v.x, v.y);
        ((__half2*)out)[2*i + 1] = __floats2half2_rn(v.z, v.w);
    }
}

__global__ __launch_bounds__(256) void f2h_w4_kernel(const float* w0, const float* w1,
                                                     const float* w2, const float* w3)
{
    const float* src = (blockIdx.y == 0) ? w0 : (blockIdx.y == 1) ? w1
                     : (blockIdx.y == 2) ? w2 : w3;
    __half* dst = (blockIdx.y == 0) ? g_wqh : (blockIdx.y == 1) ? g_wkh
                : (blockIdx.y == 2) ? g_wvh : g_woh;
    int i = blockIdx.x * blockDim.x + threadIdx.x;
    float4 v = ((const float4*)src)[i];
    ((__half2*)dst)[2*i]     = __floats2half2_rn(v.x, v.y);
    ((__half2*)dst)[2*i + 1] = __floats2half2_rn(v.z, v.w);
}

// ---------------------------------------------------------------------------
// FP16 GEMM body. 256x128 tile, BK=32, 512 threads, m16n8k16, cp.async
// double-buffered. Warp covers ONE 64-col head-half pattern:
//   col_off(fn) = (wn&1)*16 + (fn&1 ? 32 : 0) + (fn>>1 ? 8 : 0), head = wn>>1
// so rotary pairs (j, j+32) are held by the same thread (fn0<->fn1, fn2<->fn3).
// MODE: 0 = plain half out, 1 = plain fp32 out, 2 = rotary half out (qscale).
// ---------------------------------------------------------------------------
#define ASH 40
#define GA_HALVES (256*ASH)
#define GB_HALVES (128*ASH)
#define GEMM_SMEM_BYTES (2*(GA_HALVES + GB_HALVES)*2)   // 61,440 B

template<int MODE>
__device__ __forceinline__ void gemm_body(const __half* __restrict__ A,
                                          const __half* __restrict__ W,
                                          const float* __restrict__ bias,
                                          void* __restrict__ outv,
                                          const float* __restrict__ cosb,
                                          const float* __restrict__ sinb,
                                          float qscale)
{
    __half* As = (__half*)dynsm;
    __half* Bs = As + 2 * GA_HALVES;

    const int tid  = threadIdx.x;
    const int warp = tid >> 5;
    const int lane = tid & 31;
    const int g    = lane >> 2;
    const int t    = lane & 3;
    const int wm   = warp & 3;
    const int wn   = warp >> 2;

    const __half* Abase = A + (size_t)(blockIdx.y * 256) * D_;
    const __half* Wbase = W + (size_t)(blockIdx.x * 128) * D_;

    const unsigned sA = (unsigned)__cvta_generic_to_shared(As);
    const unsigned sB = (unsigned)__cvta_generic_to_shared(Bs);

    float acc[4][4][4];
    #pragma unroll
    for (int i = 0; i < 4; i++)
        #pragma unroll
        for (int j = 0; j < 4; j++)
            #pragma unroll
            for (int r = 0; r < 4; r++) acc[i][j][r] = 0.f;

    auto issue = [&](int kt, int buf) {
        const int k0 = kt * 32;
        #pragma unroll
        for (int it = 0; it < 2; it++) {
            int idx = tid + it * 512;
            int row = idx >> 2;
            int ch  = (idx & 3) * 8;
            cpa16(sA + (unsigned)(buf * GA_HALVES + row * ASH + ch) * 2,
                  Abase + (size_t)row * D_ + k0 + ch);
        }
        {
            int row = tid >> 2;
            int ch  = (tid & 3) * 8;
            cpa16(sB + (unsigned)(buf * GB_HALVES + row * ASH + ch) * 2,
                  Wbase + (size_t)row * D_ + k0 + ch);
        }
        CP_COMMIT();
    };

    issue(0, 0);
    const int NKT = D_ / 32;
    for (int kt = 0; kt < NKT; kt++) {
        const int buf = kt & 1;
        CP_WAIT0();
        __syncthreads();
        if (kt + 1 < NKT) issue(kt + 1, buf ^ 1);

        const __half* Ab = As + buf * GA_HALVES;
        const __half* Bb = Bs + buf * GB_HALVES;
        #pragma unroll
        for (int ks = 0; ks < 2; ks++) {
            const int kk = ks * 16;
            unsigned af[4][4], bf[4][2];
            #pragma unroll
            for (int fm = 0; fm < 4; fm++) {
                const int rb = wm * 64 + fm * 16;
                af[fm][0] = ldh2(&Ab[(rb + g)     * ASH + kk + 2*t]);
                af[fm][1] = ldh2(&Ab[(rb + g + 8) * ASH + kk + 2*t]);
                af[fm][2] = ldh2(&Ab[(rb + g)     * ASH + kk + 8 + 2*t]);
                af[fm][3] = ldh2(&Ab[(rb + g + 8) * ASH + kk + 8 + 2*t]);
            }
            #pragma unroll
            for (int fn = 0; fn < 4; fn++) {
                const int nb = (wn >> 1) * 64 + (wn & 1) * 16
                             + ((fn & 1) ? 32 : 0) + ((fn >> 1) ? 8 : 0);
                bf[fn][0] = ldh2(&Bb[(nb + g) * ASH + kk + 2*t]);
                bf[fn][1] = ldh2(&Bb[(nb + g) * ASH + kk + 8 + 2*t]);
            }
            #pragma unroll
            for (int fm = 0; fm < 4; fm++)
                #pragma unroll
                for (int fn = 0; fn < 4; fn++)
                    mma_f16(acc[fm][fn], af[fm][0], af[fm][1], af[fm][2], af[fm][3],
                            bf[fn][0], bf[fn][1]);
        }
    }

    // ---- epilogue ----
    #pragma unroll
    for (int fm = 0; fm < 4; fm++) {
        const int rowg = blockIdx.y * 256 + wm * 64 + fm * 16 + g;
        if (MODE == 2) {
            // rotary: pairs (fn=2p) <-> (fn=2p+1) are cols j and j+32 in-head
            const int sa0 = rowg & (S_ - 1);
            const int sa1 = (rowg + 8) & (S_ - 1);
            #pragma unroll
            for (int p = 0; p < 2; p++) {
                const int jb   = (wn & 1) * 16 + p * 8 + 2 * t;  // in-head col, < 32
                const int gcol = blockIdx.x * 128 + (wn >> 1) * 64 + jb;
                float2 bj  = *(const float2*)&bias[gcol];
                float2 bj2 = *(const float2*)&bias[gcol + 32];
                float a0 = acc[fm][2*p][0] + bj.x,  a1 = acc[fm][2*p][1] + bj.y;
                float a2 = acc[fm][2*p][2] + bj.x,  a3 = acc[fm][2*p][3] + bj.y;
                float b0 = acc[fm][2*p+1][0] + bj2.x, b1 = acc[fm][2*p+1][1] + bj2.y;
                float b2 = acc[fm][2*p+1][2] + bj2.x, b3 = acc[fm][2*p+1][3] + bj2.y;

                float2 c1r0 = *(const float2*)&cosb[sa0*HD_ + jb];
                float2 s1r0 = *(const float2*)&sinb[sa0*HD_ + jb];
                float2 c2r0 = *(const float2*)&cosb[sa0*HD_ + jb + 32];
                float2 s2r0 = *(const float2*)&sinb[sa0*HD_ + jb + 32];
                float2 c1r1 = *(const float2*)&cosb[sa1*HD_ + jb];
                float2 s1r1 = *(const float2*)&sinb[sa1*HD_ + jb];
                float2 c2r1 = *(const float2*)&cosb[sa1*HD_ + jb + 32];
                float2 s2r1 = *(const float2*)&sinb[sa1*HD_ + jb + 32];

                float o0 = (a0*c1r0.x - b0*s1r0.x) * qscale;   // row g,   col j
                float o1 = (a1*c1r0.y - b1*s1r0.y) * qscale;
                float u0 = (b0*c2r0.x + a0*s2r0.x) * qscale;   // row g,   col j+32
                float u1 = (b1*c2r0.y + a1*s2r0.y) * qscale;
                float o2 = (a2*c1r1.x - b2*s1r1.x) * qscale;   // row g+8, col j
                float o3 = (a3*c1r1.y - b3*s1r1.y) * qscale;
                float u2 = (b2*c2r1.x + a2*s2r1.x) * qscale;   // row g+8, col j+32
                float u3 = (b3*c2r1.y + a3*s2r1.y) * qscale;

                __half* out = (__half*)outv;
                *(__half2*)&out[(size_t)rowg * D_ + gcol]            = __floats2half2_rn(o0, o1);
                *(__half2*)&out[(size_t)rowg * D_ + gcol + 32]       = __floats2half2_rn(u0, u1);
                *(__half2*)&out[(size_t)(rowg + 8) * D_ + gcol]      = __floats2half2_rn(o2, o3);
                *(__half2*)&out[(size_t)(rowg + 8) * D_ + gcol + 32] = __floats2half2_rn(u2, u3);
            }
        } else {
            #pragma unroll
            for (int fn = 0; fn < 4; fn++) {
                const int col = blockIdx.x * 128 + (wn >> 1) * 64 + (wn & 1) * 16
                              + ((fn & 1) ? 32 : 0) + ((fn >> 1) ? 8 : 0) + 2 * t;
                const float bx = bias[col];
                const float by = bias[col + 1];
                if (MODE == 0) {
                    __half* out = (__half*)outv;
                    *(__half2*)&out[(size_t)rowg * D_ + col] =
                        __floats2half2_rn(acc[fm][fn][0] + bx, acc[fm][fn][1] + by);
                    *(__half2*)&out[(size_t)(rowg + 8) * D_ + col] =
                        __floats2half2_rn(acc[fm][fn][2] + bx, acc[fm][fn][3] + by);
                } else {
                    float* out = (float*)outv;
                    *(float2*)&out[(size_t)rowg * D_ + col] =
                        make_float2(acc[fm][fn][0] + bx, acc[fm][fn][1] + by);
                    *(float2*)&out[(size_t)(rowg + 8) * D_ + col] =
                        make_float2(acc[fm][fn][2] + bx, acc[fm][fn][3] + by);
                }
            }
        }
    }
}

__global__ __launch_bounds__(512) void gemm_qk(const float* __restrict__ bq,
                                               const float* __restrict__ bk,
                                               const float* __restrict__ cosb,
                                               const float* __restrict__ sinb)
{
    if (blockIdx.z == 0)
        gemm_body<2>(g_xh, g_wqh, bq, g_qh, cosb, sinb, QSCALE);
    else
        gemm_body<2>(g_xh, g_wkh, bk, g_kh, cosb, sinb, 1.0f);
}

__global__ __launch_bounds__(512) void gemm_v(const float* __restrict__ bv)
{
    gemm_body<0>(g_xh, g_wvh, bv, g_prv, 0, 0, 1.0f);
}

__global__ __launch_bounds__(512) void gemm_out(const float* __restrict__ bo,
                                                float* __restrict__ out)
{
    gemm_body<1>(g_cth, g_woh, bo, out, 0, 0, 1.0f);
}

// ---------------------------------------------------------------------------
// V transpose: half [b,s,h,d] -> half g_vt[bh][d][s]. 64s x 64d tiles.
// ---------------------------------------------------------------------------
__global__ __launch_bounds__(256) void vtrans_kernel()
{
    __shared__ float ts[64][65];
    const int bh = blockIdx.x;
    const int b  = bh >> 4;
    const int h  = bh & 15;
    const int s0 = blockIdx.y * 64;
    const int tid = threadIdx.x;

    #pragma unroll
    for (int it = 0; it < 4; it++) {
        int l  = tid + it * 256;
        int r  = l >> 4;
        int c4 = (l & 15) * 4;
        const __half2* src = (const __half2*)&g_prv[(size_t)(b*S_ + s0 + r) * D_ + h*HD_ + c4];
        float2 v0 = __half22float2(src[0]);
        float2 v1 = __half22float2(src[1]);
        ts[r][c4+0] = v0.x; ts[r][c4+1] = v0.y; ts[r][c4+2] = v1.x; ts[r][c4+3] = v1.y;
    }
    __syncthreads();

    #pragma unroll
    for (int it = 0; it < 2; it++) {
        int l  = tid + it * 256;
        int d  = l >> 3;
        int j8 = (l & 7) * 8;
        __half2* dst = (__half2*)&g_vt[(size_t)(bh*HD_ + d) * S_ + s0 + j8];
        #pragma unroll
        for (int m = 0; m < 4; m++)
            dst[m] = __floats2half2_rn(ts[j8 + 2*m][d], ts[j8 + 2*m + 1][d]);
    }
}

// ---------------------------------------------------------------------------
// FP16 flash attention, causal. Softmax in log2 domain (Q carries log2e).
// Bc=128 in two 64-wide chunks (2 CTAs/SM). 256 threads (8 warps x 16 rows).
// ---------------------------------------------------------------------------
#define PSH 72
#define KSH 72
#define VSH 136
#define P_HALVES  (128*PSH)
#define KT_HALVES (128*KSH)
#define VT_HALVES (64*VSH)
#define ATT_SMEM_BYTES ((P_HALVES + 2*KT_HALVES + 2*VT_HALVES) * 2)  // 90,112 B

__global__ __launch_bounds__(256, 2) void attn_h()
{
    __half* Ph = (__half*)dynsm;                 // [128][PSH]
    __half* Kh = Ph + P_HALVES;                  // [2][128][KSH]
    __half* Vh = Kh + 2 * KT_HALVES;             // [2][64][VSH]

    const int qt = (int)gridDim.x - 1 - (int)blockIdx.x;  // heavy tiles first
    const int bh = blockIdx.y;
    const int b  = bh >> 4;
    const int h  = bh & 15;
    const int q0 = qt * 128;

    const int tid  = threadIdx.x;
    const int warp = tid >> 5;
    const int lane = tid & 31;
    const int g    = lane >> 2;
    const int t    = lane & 3;
    const int rb   = warp * 16;

    const unsigned sP = (unsigned)__cvta_generic_to_shared(Ph);
    const unsigned sK = (unsigned)__cvta_generic_to_shared(Kh);
    const unsigned sV = (unsigned)__cvta_generic_to_shared(Vh);

    auto issueKV = [&](int kt, int buf) {
        const int k0 = kt * 128;
        #pragma unroll
        for (int it = 0; it < 4; it++) {
            int idx = tid + it * 256;
            int j   = idx >> 3;
            int ch  = (idx & 7) * 8;
            cpa16(sK + (unsigned)(buf * KT_HALVES + j * KSH + ch) * 2,
                  g_kh + (size_t)(b*S_ + k0 + j) * D_ + h*HD_ + ch);
        }
        #pragma unroll
        for (int it = 0; it < 4; it++) {
            int idx = tid + it * 256;
            int d   = idx >> 4;
            int ch  = (idx & 15) * 8;
            cpa16(sV + (unsigned)(buf * VT_HALVES + d * VSH + ch) * 2,
                  g_vt + (size_t)(bh*HD_ + d) * S_ + k0 + ch);
        }
        CP_COMMIT();
    };

    // stage Q into P buffer rows, then issue KV0
    #pragma unroll
    for (int it = 0; it < 4; it++) {
        int idx = tid + it * 256;
        int i   = idx >> 3;
        int ch  = (idx & 7) * 8;
        cpa16(sP + (unsigned)(i * PSH + ch) * 2,
              g_qh + (size_t)(b*S_ + q0 + i) * D_ + h*HD_ + ch);
    }
    issueKV(0, 0);
    CP_WAIT0();
    __syncthreads();

    unsigned qa[4][4];
    #pragma unroll
    for (int ks = 0; ks < 4; ks++) {
        int kk = ks * 16;
        qa[ks][0] = ldh2(&Ph[(rb + g)     * PSH + kk + 2*t]);
        qa[ks][1] = ldh2(&Ph[(rb + g + 8) * PSH + kk + 2*t]);
        qa[ks][2] = ldh2(&Ph[(rb + g)     * PSH + kk + 8 + 2*t]);
        qa[ks][3] = ldh2(&Ph[(rb + g + 8) * PSH + kk + 8 + 2*t]);
    }
    // From here Ph rows [rb, rb+16) are warp-private (P buffer, 64 cols).

    float m_lo = -1e30f, m_hi = -1e30f, l_lo = 0.f, l_hi = 0.f;
    float oacc[8][4];
    #pragma unroll
    for (int nf = 0; nf < 8; nf++)
        #pragma unroll
        for (int r = 0; r < 4; r++) oacc[nf][r] = 0.f;

    const int nkt = qt + 1;
    for (int kt = 0; kt < nkt; kt++) {
        const int buf = kt & 1;
        const int k0  = kt * 128;
        CP_WAIT0();
        __syncthreads();
        if (kt + 1 < nkt) issueKV(kt + 1, buf ^ 1);

        const __half* Kb = Kh + buf * KT_HALVES;
        const __half* Vb = Vh + buf * VT_HALVES;

        #pragma unroll
        for (int c = 0; c < 2; c++) {
            const int j0 = c * 64;
            if (kt == nkt - 1 && j0 > rb + 15) continue;  // fully masked chunk

            float sacc[8][4];
            #pragma unroll
            for (int nf = 0; nf < 8; nf++)
                #pragma unroll
                for (int r = 0; r < 4; r++) sacc[nf][r] = 0.f;

            #pragma unroll
            for (int ks = 0; ks < 4; ks++) {
                int kk = ks * 16;
                #pragma unroll
                for (int nf = 0; nf < 8; nf++) {
                    unsigned b0 = ldh2(&Kb[(j0 + nf*8 + g) * KSH + kk + 2*t]);
                    unsigned b1 = ldh2(&Kb[(j0 + nf*8 + g) * KSH + kk + 8 + 2*t]);
                    mma_f16(sacc[nf], qa[ks][0], qa[ks][1], qa[ks][2], qa[ks][3], b0, b1);
                }
            }

            if (kt == nkt - 1) {
                const int rlo = q0 + rb + g;
                #pragma unroll
                for (int nf = 0; nf < 8; nf++) {
                    int c0 = k0 + j0 + nf*8 + 2*t;
                    int c1 = c0 + 1;
                    if (c0 > rlo)     sacc[nf][0] = -1e30f;
                    if (c1 > rlo)     sacc[nf][1] = -1e30f;
                    if (c0 > rlo + 8) sacc[nf][2] = -1e30f;
                    if (c1 > rlo + 8) sacc[nf][3] = -1e30f;
                }
            }

            // ---- online softmax in log2 domain ----
            float mx_lo = -1e30f, mx_hi = -1e30f;
            #pragma unroll
            for (int nf = 0; nf < 8; nf++) {
                mx_lo = fmaxf(mx_lo, fmaxf(sacc[nf][0], sacc[nf][1]));
                mx_hi = fmaxf(mx_hi, fmaxf(sacc[nf][2], sacc[nf][3]));
            }
            mx_lo = fmaxf(mx_lo, __shfl_xor_sync(0xffffffffu, mx_lo, 1));
            mx_lo = fmaxf(mx_lo, __shfl_xor_sync(0xffffffffu, mx_lo, 2));
            mx_hi = fmaxf(mx_hi, __shfl_xor_sync(0xffffffffu, mx_hi, 1));
            mx_hi = fmaxf(mx_hi, __shfl_xor_sync(0xffffffffu, mx_hi, 2));

            float mn_lo = fmaxf(m_lo, mx_lo);
            float mn_hi = fmaxf(m_hi, mx_hi);
            float r_lo  = ex2f(m_lo - mn_lo);
            float r_hi  = ex2f(m_hi - mn_hi);

            float sum_lo = 0.f, sum_hi = 0.f;
            #pragma unroll
            for (int nf = 0; nf < 8; nf++) {
                sacc[nf][0] = ex2f(sacc[nf][0] - mn_lo);
                sacc[nf][1] = ex2f(sacc[nf][1] - mn_lo);
                sacc[nf][2] = ex2f(sacc[nf][2] - mn_hi);
                sacc[nf][3] = ex2f(sacc[nf][3] - mn_hi);
                sum_lo += sacc[nf][0] + sacc[nf][1];
                sum_hi += sacc[nf][2] + sacc[nf][3];
            }
            sum_lo += __shfl_xor_sync(0xffffffffu, sum_lo, 1);
            sum_lo += __shfl_xor_sync(0xffffffffu, sum_lo, 2);
            sum_hi += __shfl_xor_sync(0xffffffffu, sum_hi, 1);
            sum_hi += __shfl_xor_sync(0xffffffffu, sum_hi, 2);

            l_lo = l_lo * r_lo + sum_lo;  m_lo = mn_lo;
            l_hi = l_hi * r_hi + sum_hi;  m_hi = mn_hi;

            #pragma unroll
            for (int nf = 0; nf < 8; nf++) {
                oacc[nf][0] *= r_lo;  oacc[nf][1] *= r_lo;
                oacc[nf][2] *= r_hi;  oacc[nf][3] *= r_hi;
            }

            #pragma unroll
            for (int nf = 0; nf < 8; nf++) {
                *(__half2*)&Ph[(rb + g)     * PSH + nf*8 + 2*t] =
                    __floats2half2_rn(sacc[nf][0], sacc[nf][1]);
                *(__half2*)&Ph[(rb + g + 8) * PSH + nf*8 + 2*t] =
                    __floats2half2_rn(sacc[nf][2], sacc[nf][3]);
            }
            __syncwarp();

            #pragma unroll
            for (int ks = 0; ks < 4; ks++) {
                int kk = ks * 16;
                unsigned p0 = ldh2(&Ph[(rb + g)     * PSH + kk + 2*t]);
                unsigned p1 = ldh2(&Ph[(rb + g + 8) * PSH + kk + 2*t]);
                unsigned p2 = ldh2(&Ph[(rb + g)     * PSH + kk + 8 + 2*t]);
                unsigned p3 = ldh2(&Ph[(rb + g + 8) * PSH + kk + 8 + 2*t]);
                #pragma unroll
                for (int nf = 0; nf < 8; nf++) {
                    unsigned b0 = ldh2(&Vb[(nf*8 + g) * VSH + j0 + kk + 2*t]);
                    unsigned b1 = ldh2(&Vb[(nf*8 + g) * VSH + j0 + kk + 8 + 2*t]);
                    mma_f16(oacc[nf], p0, p1, p2, p3, b0, b1);
                }
            }
            __syncwarp();
        }
    }

    const float inv_lo = 1.f / l_lo;
    const float inv_hi = 1.f / l_hi;
    #pragma unroll
    for (int nf = 0; nf < 8; nf++) {
        size_t off = (size_t)(b*S_ + q0 + rb + g) * D_ + h*HD_ + nf*8 + 2*t;
        *(__half2*)&g_cth[off] =
            __floats2half2_rn(oacc[nf][0] * inv_lo, oacc[nf][1] * inv_lo);
        *(__half2*)&g_cth[off + (size_t)8 * D_] =
            __floats2half2_rn(oacc[nf][2] * inv_hi, oacc[nf][3] * inv_hi);
    }
}

// ---------------------------------------------------------------------------
extern "C" void kernel_launch(void* const* d_in, const int* in_sizes, int n_in,
                              void* d_out, int out_size)
{
    const float* x    = (const float*)d_in[0];
    const float* cosb = (const float*)d_in[1];
    const float* sinb = (const float*)d_in[2];
    // d_in[3] = attn_mask (causal; implemented analytically)
    const float* Wq = (const float*)d_in[4];
    const float* bq = (const float*)d_in[5];
    const float* Wk = (const float*)d_in[6];
    const float* bk = (const float*)d_in[7];
    const float* Wv = (const float*)d_in[8];
    const float* bv = (const float*)d_in[9];
    const float* Wo = (const float*)d_in[10];
    const float* bo = (const float*)d_in[11];
    float* out = (float*)d_out;

    __half* xh;
    cudaGetSymbolAddress((void**)&xh, g_xh);

    cudaFuncSetAttribute(gemm_qk,
                         cudaFuncAttributeMaxDynamicSharedMemorySize,
                         GEMM_SMEM_BYTES);
    cudaFuncSetAttribute(gemm_v,
                         cudaFuncAttributeMaxDynamicSharedMemorySize,
                         GEMM_SMEM_BYTES);
    cudaFuncSetAttribute(gemm_out,
                         cudaFuncAttributeMaxDynamicSharedMemorySize,
                         GEMM_SMEM_BYTES);
    cudaFuncSetAttribute(attn_h,
                         cudaFuncAttributeMaxDynamicSharedMemorySize,
                         ATT_SMEM_BYTES);

    f2h_kernel<<<(M_*D_/4 + 255)/256, 256>>>(x, xh, M_*D_/4);
    f2h_w4_kernel<<<dim3(D_*D_/4/256, 4), 256>>>(Wq, Wk, Wv, Wo);

    gemm_qk<<<dim3(D_/128, M_/256, 2), 512, GEMM_SMEM_BYTES>>>(bq, bk, cosb, sinb);
    gemm_v<<<dim3(D_/128, M_/256), 512, GEMM_SMEM_BYTES>>>(bv);

    vtrans_kernel<<<dim3(B_*H_, S_/64), 256>>>();

    attn_h<<<dim3(S_/128, B_*H_), 256, ATT_SMEM_BYTES>>>();

    gemm_out<<<dim3(D_/128, M_/256), 512, GEMM_SMEM_BYTES>>>(bo, out);
}

// round 16
// speedup vs baseline: 1.0596x; 1.0596x over previous
#include <cuda_runtime.h>
#include <cuda_fp16.h>
#include <math.h>

#define B_  4
#define S_  2048
#define D_  1024
#define H_  16
#define HD_ 64
#define M_  (B_*S_)

// Q scale: 1/8 (=HD^-0.5) times log2(e), so softmax can use raw ex2.
#define QSCALE 0.18033688011112042f

// Scratch (allocation-free rule: __device__ globals)
__device__ __half g_xh[M_*D_];         // half input x
__device__ __half g_wqh[D_*D_];
__device__ __half g_wkh[D_*D_];
__device__ __half g_wvh[D_*D_];
__device__ __half g_woh[D_*D_];
__device__ __half g_prv[M_*D_];        // V projection (half)
__device__ __half g_qh[M_*D_];         // rotary'd Q x QSCALE
__device__ __half g_kh[M_*D_];         // rotary'd K
__device__ __half g_vt[M_*D_];         // V transposed: [B*H][64][2048]
__device__ __half g_cth[M_*D_];        // attention output (half)

extern __shared__ float dynsm[];

__device__ __forceinline__ void mma_f16(float* c,
                                        unsigned a0, unsigned a1, unsigned a2, unsigned a3,
                                        unsigned b0, unsigned b1)
{
    asm volatile(
        "mma.sync.aligned.m16n8k16.row.col.f32.f16.f16.f32 "
        "{%0,%1,%2,%3}, {%4,%5,%6,%7}, {%8,%9}, {%0,%1,%2,%3};"
        : "+f"(c[0]), "+f"(c[1]), "+f"(c[2]), "+f"(c[3])
        : "r"(a0), "r"(a1), "r"(a2), "r"(a3), "r"(b0), "r"(b1));
}

__device__ __forceinline__ void cpa16(unsigned saddr, const void* gptr) {
    asm volatile("cp.async.cg.shared.global [%0], [%1], 16;" :: "r"(saddr), "l"(gptr));
}
#define CP_COMMIT() asm volatile("cp.async.commit_group;")
#define CP_WAIT0()  asm volatile("cp.async.wait_group 0;")

__device__ __forceinline__ unsigned ldh2(const __half* p) {
    return *(const unsigned*)p;
}
__device__ __forceinline__ float ex2f(float x) {
    float y;
    asm("ex2.approx.f32 %0, %1;" : "=f"(y) : "f"(x));
    return y;
}

// ---------------------------------------------------------------------------
// fp32 -> half conversions
// ---------------------------------------------------------------------------
__global__ __launch_bounds__(256) void f2h_kernel(const float* __restrict__ in,
                                                  __half* __restrict__ out, int n4)
{
    int i = blockIdx.x * blockDim.x + threadIdx.x;
    if (i < n4) {
        float4 v = ((const float4*)in)[i];
        ((__half2*)out)[2*i]     = __floats2half2_rn(v.x, v.y);
        ((__half2*)out)[2*i + 1] = __floats2half2_rn(v.z, v.w);
    }
}

__global__ __launch_bounds__(256) void f2h_w4_kernel(const float* w0, const float* w1,
                                                     const float* w2, const float* w3)
{
    const float* src = (blockIdx.y == 0) ? w0 : (blockIdx.y == 1) ? w1
                     : (blockIdx.y == 2) ? w2 : w3;
    __half* dst = (blockIdx.y == 0) ? g_wqh : (blockIdx.y == 1) ? g_wkh
                : (blockIdx.y == 2) ? g_wvh : g_woh;
    int i = blockIdx.x * blockDim.x + threadIdx.x;
    float4 v = ((const float4*)src)[i];
    ((__half2*)dst)[2*i]     = __floats2half2_rn(v.x, v.y);
    ((__half2*)dst)[2*i + 1] = __floats2half2_rn(v.z, v.w);
}

// ---------------------------------------------------------------------------
// FP16 GEMM body. 128x128 tile, BK=32, 256 threads (8 warps, warp tile
// 64x32), __launch_bounds__(256,2) -> 2 CTAs/SM (32 warps). cp.async
// double-buffered. Warp N-mapping keeps rotary pairs (j, j+32) in-thread:
//   rows: (warp&1)*64 + fm*16 ; cols: (wn>>1)*64 + (wn&1)*16 + (fn&1)*32
//         + (fn>>1)*8, wn = warp>>1.
// MODE: 0 = plain half out, 1 = plain fp32 out, 2 = rotary half out (qscale).
// ---------------------------------------------------------------------------
#define ASH 40
#define GA_HALVES (128*ASH)
#define GB_HALVES (128*ASH)
#define GEMM_SMEM_BYTES (2*(GA_HALVES + GB_HALVES)*2)   // 40,960 B

template<int MODE>
__device__ __forceinline__ void gemm_body(const __half* __restrict__ A,
                                          const __half* __restrict__ W,
                                          const float* __restrict__ bias,
                                          void* __restrict__ outv,
                                          const float* __restrict__ cosb,
                                          const float* __restrict__ sinb,
                                          float qscale)
{
    __half* As = (__half*)dynsm;
    __half* Bs = As + 2 * GA_HALVES;

    const int tid  = threadIdx.x;
    const int warp = tid >> 5;
    const int lane = tid & 31;
    const int g    = lane >> 2;
    const int t    = lane & 3;
    const int wm   = warp & 1;     // 2 x 64 rows
    const int wn   = warp >> 1;    // 4 x 32 cols

    const __half* Abase = A + (size_t)(blockIdx.y * 128) * D_;
    const __half* Wbase = W + (size_t)(blockIdx.x * 128) * D_;

    const unsigned sA = (unsigned)__cvta_generic_to_shared(As);
    const unsigned sB = (unsigned)__cvta_generic_to_shared(Bs);

    float acc[4][4][4];
    #pragma unroll
    for (int i = 0; i < 4; i++)
        #pragma unroll
        for (int j = 0; j < 4; j++)
            #pragma unroll
            for (int r = 0; r < 4; r++) acc[i][j][r] = 0.f;

    auto issue = [&](int kt, int buf) {
        const int k0 = kt * 32;
        #pragma unroll
        for (int it = 0; it < 2; it++) {       // A: 128 rows x 4 chunks = 512
            int idx = tid + it * 256;
            int row = idx >> 2;
            int ch  = (idx & 3) * 8;
            cpa16(sA + (unsigned)(buf * GA_HALVES + row * ASH + ch) * 2,
                  Abase + (size_t)row * D_ + k0 + ch);
        }
        #pragma unroll
        for (int it = 0; it < 2; it++) {       // B: 128 rows x 4 chunks = 512
            int idx = tid + it * 256;
            int row = idx >> 2;
            int ch  = (idx & 3) * 8;
            cpa16(sB + (unsigned)(buf * GB_HALVES + row * ASH + ch) * 2,
                  Wbase + (size_t)row * D_ + k0 + ch);
        }
        CP_COMMIT();
    };

    issue(0, 0);
    const int NKT = D_ / 32;
    for (int kt = 0; kt < NKT; kt++) {
        const int buf = kt & 1;
        CP_WAIT0();
        __syncthreads();
        if (kt + 1 < NKT) issue(kt + 1, buf ^ 1);

        const __half* Ab = As + buf * GA_HALVES;
        const __half* Bb = Bs + buf * GB_HALVES;
        #pragma unroll
        for (int ks = 0; ks < 2; ks++) {
            const int kk = ks * 16;
            unsigned af[4][4], bf[4][2];
            #pragma unroll
            for (int fm = 0; fm < 4; fm++) {
                const int rb = wm * 64 + fm * 16;
                af[fm][0] = ldh2(&Ab[(rb + g)     * ASH + kk + 2*t]);
                af[fm][1] = ldh2(&Ab[(rb + g + 8) * ASH + kk + 2*t]);
                af[fm][2] = ldh2(&Ab[(rb + g)     * ASH + kk + 8 + 2*t]);
                af[fm][3] = ldh2(&Ab[(rb + g + 8) * ASH + kk + 8 + 2*t]);
            }
            #pragma unroll
            for (int fn = 0; fn < 4; fn++) {
                const int nb = (wn >> 1) * 64 + (wn & 1) * 16
                             + ((fn & 1) ? 32 : 0) + ((fn >> 1) ? 8 : 0);
                bf[fn][0] = ldh2(&Bb[(nb + g) * ASH + kk + 2*t]);
                bf[fn][1] = ldh2(&Bb[(nb + g) * ASH + kk + 8 + 2*t]);
            }
            #pragma unroll
            for (int fm = 0; fm < 4; fm++)
                #pragma unroll
                for (int fn = 0; fn < 4; fn++)
                    mma_f16(acc[fm][fn], af[fm][0], af[fm][1], af[fm][2], af[fm][3],
                            bf[fn][0], bf[fn][1]);
        }
    }

    // ---- epilogue ----
    #pragma unroll
    for (int fm = 0; fm < 4; fm++) {
        const int rowg = blockIdx.y * 128 + wm * 64 + fm * 16 + g;
        if (MODE == 2) {
            const int sa0 = rowg & (S_ - 1);
            const int sa1 = (rowg + 8) & (S_ - 1);
            #pragma unroll
            for (int p = 0; p < 2; p++) {
                const int jb   = (wn & 1) * 16 + p * 8 + 2 * t;  // in-head col, < 32
                const int gcol = blockIdx.x * 128 + (wn >> 1) * 64 + jb;
                float2 bj  = *(const float2*)&bias[gcol];
                float2 bj2 = *(const float2*)&bias[gcol + 32];
                float a0 = acc[fm][2*p][0] + bj.x,  a1 = acc[fm][2*p][1] + bj.y;
                float a2 = acc[fm][2*p][2] + bj.x,  a3 = acc[fm][2*p][3] + bj.y;
                float b0 = acc[fm][2*p+1][0] + bj2.x, b1 = acc[fm][2*p+1][1] + bj2.y;
                float b2 = acc[fm][2*p+1][2] + bj2.x, b3 = acc[fm][2*p+1][3] + bj2.y;

                float2 c1r0 = *(const float2*)&cosb[sa0*HD_ + jb];
                float2 s1r0 = *(const float2*)&sinb[sa0*HD_ + jb];
                float2 c2r0 = *(const float2*)&cosb[sa0*HD_ + jb + 32];
                float2 s2r0 = *(const float2*)&sinb[sa0*HD_ + jb + 32];
                float2 c1r1 = *(const float2*)&cosb[sa1*HD_ + jb];
                float2 s1r1 = *(const float2*)&sinb[sa1*HD_ + jb];
                float2 c2r1 = *(const float2*)&cosb[sa1*HD_ + jb + 32];
                float2 s2r1 = *(const float2*)&sinb[sa1*HD_ + jb + 32];

                float o0 = (a0*c1r0.x - b0*s1r0.x) * qscale;
                float o1 = (a1*c1r0.y - b1*s1r0.y) * qscale;
                float u0 = (b0*c2r0.x + a0*s2r0.x) * qscale;
                float u1 = (b1*c2r0.y + a1*s2r0.y) * qscale;
                float o2 = (a2*c1r1.x - b2*s1r1.x) * qscale;
                float o3 = (a3*c1r1.y - b3*s1r1.y) * qscale;
                float u2 = (b2*c2r1.x + a2*s2r1.x) * qscale;
                float u3 = (b3*c2r1.y + a3*s2r1.y) * qscale;

                __half* out = (__half*)outv;
                *(__half2*)&out[(size_t)rowg * D_ + gcol]            = __floats2half2_rn(o0, o1);
                *(__half2*)&out[(size_t)rowg * D_ + gcol + 32]       = __floats2half2_rn(u0, u1);
                *(__half2*)&out[(size_t)(rowg + 8) * D_ + gcol]      = __floats2half2_rn(o2, o3);
                *(__half2*)&out[(size_t)(rowg + 8) * D_ + gcol + 32] = __floats2half2_rn(u2, u3);
            }
        } else {
            #pragma unroll
            for (int fn = 0; fn < 4; fn++) {
                const int col = blockIdx.x * 128 + (wn >> 1) * 64 + (wn & 1) * 16
                              + ((fn & 1) ? 32 : 0) + ((fn >> 1) ? 8 : 0) + 2 * t;
                const float bx = bias[col];
                const float by = bias[col + 1];
                if (MODE == 0) {
                    __half* out = (__half*)outv;
                    *(__half2*)&out[(size_t)rowg * D_ + col] =
                        __floats2half2_rn(acc[fm][fn][0] + bx, acc[fm][fn][1] + by);
                    *(__half2*)&out[(size_t)(rowg + 8) * D_ + col] =
                        __floats2half2_rn(acc[fm][fn][2] + bx, acc[fm][fn][3] + by);
                } else {
                    float* out = (float*)outv;
                    *(float2*)&out[(size_t)rowg * D_ + col] =
                        make_float2(acc[fm][fn][0] + bx, acc[fm][fn][1] + by);
                    *(float2*)&out[(size_t)(rowg + 8) * D_ + col] =
                        make_float2(acc[fm][fn][2] + bx, acc[fm][fn][3] + by);
                }
            }
        }
    }
}

__global__ __launch_bounds__(256, 2) void gemm_qkv(const float* __restrict__ bq,
                                                   const float* __restrict__ bk,
                                                   const float* __restrict__ bv,
                                                   const float* __restrict__ cosb,
                                                   const float* __restrict__ sinb)
{
    if (blockIdx.z == 0)
        gemm_body<2>(g_xh, g_wqh, bq, g_qh, cosb, sinb, QSCALE);
    else if (blockIdx.z == 1)
        gemm_body<2>(g_xh, g_wkh, bk, g_kh, cosb, sinb, 1.0f);
    else
        gemm_body<0>(g_xh, g_wvh, bv, g_prv, 0, 0, 1.0f);
}

__global__ __launch_bounds__(256, 2) void gemm_out(const float* __restrict__ bo,
                                                   float* __restrict__ out)
{
    gemm_body<1>(g_cth, g_woh, bo, out, 0, 0, 1.0f);
}

// ---------------------------------------------------------------------------
// V transpose: half [b,s,h,d] -> half g_vt[bh][d][s]. 64s x 64d tiles.
// ---------------------------------------------------------------------------
__global__ __launch_bounds__(256) void vtrans_kernel()
{
    __shared__ float ts[64][65];
    const int bh = blockIdx.x;
    const int b  = bh >> 4;
    const int h  = bh & 15;
    const int s0 = blockIdx.y * 64;
    const int tid = threadIdx.x;

    #pragma unroll
    for (int it = 0; it < 4; it++) {
        int l  = tid + it * 256;
        int r  = l >> 4;
        int c4 = (l & 15) * 4;
        const __half2* src = (const __half2*)&g_prv[(size_t)(b*S_ + s0 + r) * D_ + h*HD_ + c4];
        float2 v0 = __half22float2(src[0]);
        float2 v1 = __half22float2(src[1]);
        ts[r][c4+0] = v0.x; ts[r][c4+1] = v0.y; ts[r][c4+2] = v1.x; ts[r][c4+3] = v1.y;
    }
    __syncthreads();

    #pragma unroll
    for (int it = 0; it < 2; it++) {
        int l  = tid + it * 256;
        int d  = l >> 3;
        int j8 = (l & 7) * 8;
        __half2* dst = (__half2*)&g_vt[(size_t)(bh*HD_ + d) * S_ + s0 + j8];
        #pragma unroll
        for (int m = 0; m < 4; m++)
            dst[m] = __floats2half2_rn(ts[j8 + 2*m][d], ts[j8 + 2*m + 1][d]);
    }
}

// ---------------------------------------------------------------------------
// FP16 flash attention, causal. Softmax in log2 domain (Q carries log2e).
// Bc=128 in two 64-wide chunks (2 CTAs/SM). 256 threads (8 warps x 16 rows).
// ---------------------------------------------------------------------------
#define PSH 72
#define KSH 72
#define VSH 136
#define P_HALVES  (128*PSH)
#define KT_HALVES (128*KSH)
#define VT_HALVES (64*VSH)
#define ATT_SMEM_BYTES ((P_HALVES + 2*KT_HALVES + 2*VT_HALVES) * 2)  // 90,112 B

__global__ __launch_bounds__(256, 2) void attn_h()
{
    __half* Ph = (__half*)dynsm;                 // [128][PSH]
    __half* Kh = Ph + P_HALVES;                  // [2][128][KSH]
    __half* Vh = Kh + 2 * KT_HALVES;             // [2][64][VSH]

    const int qt = (int)gridDim.x - 1 - (int)blockIdx.x;  // heavy tiles first
    const int bh = blockIdx.y;
    const int b  = bh >> 4;
    const int h  = bh & 15;
    const int q0 = qt * 128;

    const int tid  = threadIdx.x;
    const int warp = tid >> 5;
    const int lane = tid & 31;
    const int g    = lane >> 2;
    const int t    = lane & 3;
    const int rb   = warp * 16;

    const unsigned sP = (unsigned)__cvta_generic_to_shared(Ph);
    const unsigned sK = (unsigned)__cvta_generic_to_shared(Kh);
    const unsigned sV = (unsigned)__cvta_generic_to_shared(Vh);

    auto issueKV = [&](int kt, int buf) {
        const int k0 = kt * 128;
        #pragma unroll
        for (int it = 0; it < 4; it++) {
            int idx = tid + it * 256;
            int j   = idx >> 3;
            int ch  = (idx & 7) * 8;
            cpa16(sK + (unsigned)(buf * KT_HALVES + j * KSH + ch) * 2,
                  g_kh + (size_t)(b*S_ + k0 + j) * D_ + h*HD_ + ch);
        }
        #pragma unroll
        for (int it = 0; it < 4; it++) {
            int idx = tid + it * 256;
            int d   = idx >> 4;
            int ch  = (idx & 15) * 8;
            cpa16(sV + (unsigned)(buf * VT_HALVES + d * VSH + ch) * 2,
                  g_vt + (size_t)(bh*HD_ + d) * S_ + k0 + ch);
        }
        CP_COMMIT();
    };

    // stage Q into P buffer rows, then issue KV0
    #pragma unroll
    for (int it = 0; it < 4; it++) {
        int idx = tid + it * 256;
        int i   = idx >> 3;
        int ch  = (idx & 7) * 8;
        cpa16(sP + (unsigned)(i * PSH + ch) * 2,
              g_qh + (size_t)(b*S_ + q0 + i) * D_ + h*HD_ + ch);
    }
    issueKV(0, 0);
    CP_WAIT0();
    __syncthreads();

    unsigned qa[4][4];
    #pragma unroll
    for (int ks = 0; ks < 4; ks++) {
        int kk = ks * 16;
        qa[ks][0] = ldh2(&Ph[(rb + g)     * PSH + kk + 2*t]);
        qa[ks][1] = ldh2(&Ph[(rb + g + 8) * PSH + kk + 2*t]);
        qa[ks][2] = ldh2(&Ph[(rb + g)     * PSH + kk + 8 + 2*t]);
        qa[ks][3] = ldh2(&Ph[(rb + g + 8) * PSH + kk + 8 + 2*t]);
    }
    // From here Ph rows [rb, rb+16) are warp-private (P buffer, 64 cols).

    float m_lo = -1e30f, m_hi = -1e30f, l_lo = 0.f, l_hi = 0.f;
    float oacc[8][4];
    #pragma unroll
    for (int nf = 0; nf < 8; nf++)
        #pragma unroll
        for (int r = 0; r < 4; r++) oacc[nf][r] = 0.f;

    const int nkt = qt + 1;
    for (int kt = 0; kt < nkt; kt++) {
        const int buf = kt & 1;
        const int k0  = kt * 128;
        CP_WAIT0();
        __syncthreads();
        if (kt + 1 < nkt) issueKV(kt + 1, buf ^ 1);

        const __half* Kb = Kh + buf * KT_HALVES;
        const __half* Vb = Vh + buf * VT_HALVES;

        #pragma unroll
        for (int c = 0; c < 2; c++) {
            const int j0 = c * 64;
            if (kt == nkt - 1 && j0 > rb + 15) continue;  // fully masked chunk

            float sacc[8][4];
            #pragma unroll
            for (int nf = 0; nf < 8; nf++)
                #pragma unroll
                for (int r = 0; r < 4; r++) sacc[nf][r] = 0.f;

            #pragma unroll
            for (int ks = 0; ks < 4; ks++) {
                int kk = ks * 16;
                #pragma unroll
                for (int nf = 0; nf < 8; nf++) {
                    unsigned b0 = ldh2(&Kb[(j0 + nf*8 + g) * KSH + kk + 2*t]);
                    unsigned b1 = ldh2(&Kb[(j0 + nf*8 + g) * KSH + kk + 8 + 2*t]);
                    mma_f16(sacc[nf], qa[ks][0], qa[ks][1], qa[ks][2], qa[ks][3], b0, b1);
                }
            }

            if (kt == nkt - 1) {
                const int rlo = q0 + rb + g;
                #pragma unroll
                for (int nf = 0; nf < 8; nf++) {
                    int c0 = k0 + j0 + nf*8 + 2*t;
                    int c1 = c0 + 1;
                    if (c0 > rlo)     sacc[nf][0] = -1e30f;
                    if (c1 > rlo)     sacc[nf][1] = -1e30f;
                    if (c0 > rlo + 8) sacc[nf][2] = -1e30f;
                    if (c1 > rlo + 8) sacc[nf][3] = -1e30f;
                }
            }

            // ---- online softmax in log2 domain ----
            float mx_lo = -1e30f, mx_hi = -1e30f;
            #pragma unroll
            for (int nf = 0; nf < 8; nf++) {
                mx_lo = fmaxf(mx_lo, fmaxf(sacc[nf][0], sacc[nf][1]));
                mx_hi = fmaxf(mx_hi, fmaxf(sacc[nf][2], sacc[nf][3]));
            }
            mx_lo = fmaxf(mx_lo, __shfl_xor_sync(0xffffffffu, mx_lo, 1));
            mx_lo = fmaxf(mx_lo, __shfl_xor_sync(0xffffffffu, mx_lo, 2));
            mx_hi = fmaxf(mx_hi, __shfl_xor_sync(0xffffffffu, mx_hi, 1));
            mx_hi = fmaxf(mx_hi, __shfl_xor_sync(0xffffffffu, mx_hi, 2));

            float mn_lo = fmaxf(m_lo, mx_lo);
            float mn_hi = fmaxf(m_hi, mx_hi);
            float r_lo  = ex2f(m_lo - mn_lo);
            float r_hi  = ex2f(m_hi - mn_hi);

            float sum_lo = 0.f, sum_hi = 0.f;
            #pragma unroll
            for (int nf = 0; nf < 8; nf++) {
                sacc[nf][0] = ex2f(sacc[nf][0] - mn_lo);
                sacc[nf][1] = ex2f(sacc[nf][1] - mn_lo);
                sacc[nf][2] = ex2f(sacc[nf][2] - mn_hi);
                sacc[nf][3] = ex2f(sacc[nf][3] - mn_hi);
                sum_lo += sacc[nf][0] + sacc[nf][1];
                sum_hi += sacc[nf][2] + sacc[nf][3];
            }
            sum_lo += __shfl_xor_sync(0xffffffffu, sum_lo, 1);
            sum_lo += __shfl_xor_sync(0xffffffffu, sum_lo, 2);
            sum_hi += __shfl_xor_sync(0xffffffffu, sum_hi, 1);
            sum_hi += __shfl_xor_sync(0xffffffffu, sum_hi, 2);

            l_lo = l_lo * r_lo + sum_lo;  m_lo = mn_lo;
            l_hi = l_hi * r_hi + sum_hi;  m_hi = mn_hi;

            #pragma unroll
            for (int nf = 0; nf < 8; nf++) {
                oacc[nf][0] *= r_lo;  oacc[nf][1] *= r_lo;
                oacc[nf][2] *= r_hi;  oacc[nf][3] *= r_hi;
            }

            #pragma unroll
            for (int nf = 0; nf < 8; nf++) {
                *(__half2*)&Ph[(rb + g)     * PSH + nf*8 + 2*t] =
                    __floats2half2_rn(sacc[nf][0], sacc[nf][1]);
                *(__half2*)&Ph[(rb + g + 8) * PSH + nf*8 + 2*t] =
                    __floats2half2_rn(sacc[nf][2], sacc[nf][3]);
            }
            __syncwarp();

            #pragma unroll
            for (int ks = 0; ks < 4; ks++) {
                int kk = ks * 16;
                unsigned p0 = ldh2(&Ph[(rb + g)     * PSH + kk + 2*t]);
                unsigned p1 = ldh2(&Ph[(rb + g + 8) * PSH + kk + 2*t]);
                unsigned p2 = ldh2(&Ph[(rb + g)     * PSH + kk + 8 + 2*t]);
                unsigned p3 = ldh2(&Ph[(rb + g + 8) * PSH + kk + 8 + 2*t]);
                #pragma unroll
                for (int nf = 0; nf < 8; nf++) {
                    unsigned b0 = ldh2(&Vb[(nf*8 + g) * VSH + j0 + kk + 2*t]);
                    unsigned b1 = ldh2(&Vb[(nf*8 + g) * VSH + j0 + kk + 8 + 2*t]);
                    mma_f16(oacc[nf], p0, p1, p2, p3, b0, b1);
                }
            }
            __syncwarp();
        }
    }

    const float inv_lo = 1.f / l_lo;
    const float inv_hi = 1.f / l_hi;
    #pragma unroll
    for (int nf = 0; nf < 8; nf++) {
        size_t off = (size_t)(b*S_ + q0 + rb + g) * D_ + h*HD_ + nf*8 + 2*t;
        *(__half2*)&g_cth[off] =
            __floats2half2_rn(oacc[nf][0] * inv_lo, oacc[nf][1] * inv_lo);
        *(__half2*)&g_cth[off + (size_t)8 * D_] =
            __floats2half2_rn(oacc[nf][2] * inv_hi, oacc[nf][3] * inv_hi);
    }
}

// ---------------------------------------------------------------------------
extern "C" void kernel_launch(void* const* d_in, const int* in_sizes, int n_in,
                              void* d_out, int out_size)
{
    const float* x    = (const float*)d_in[0];
    const float* cosb = (const float*)d_in[1];
    const float* sinb = (const float*)d_in[2];
    // d_in[3] = attn_mask (causal; implemented analytically)
    const float* Wq = (const float*)d_in[4];
    const float* bq = (const float*)d_in[5];
    const float* Wk = (const float*)d_in[6];
    const float* bk = (const float*)d_in[7];
    const float* Wv = (const float*)d_in[8];
    const float* bv = (const float*)d_in[9];
    const float* Wo = (const float*)d_in[10];
    const float* bo = (const float*)d_in[11];
    float* out = (float*)d_out;

    __half* xh;
    cudaGetSymbolAddress((void**)&xh, g_xh);

    cudaFuncSetAttribute(gemm_qkv,
                         cudaFuncAttributeMaxDynamicSharedMemorySize,
                         GEMM_SMEM_BYTES);
    cudaFuncSetAttribute(gemm_out,
                         cudaFuncAttributeMaxDynamicSharedMemorySize,
                         GEMM_SMEM_BYTES);
    cudaFuncSetAttribute(attn_h,
                         cudaFuncAttributeMaxDynamicSharedMemorySize,
                         ATT_SMEM_BYTES);

    f2h_kernel<<<(M_*D_/4 + 255)/256, 256>>>(x, xh, M_*D_/4);
    f2h_w4_kernel<<<dim3(D_*D_/4/256, 4), 256>>>(Wq, Wk, Wv, Wo);

    gemm_qkv<<<dim3(D_/128, M_/128, 3), 256, GEMM_SMEM_BYTES>>>(bq, bk, bv, cosb, sinb);

    vtrans_kernel<<<dim3(B_*H_, S_/64), 256>>>();

    attn_h<<<dim3(S_/128, B_*H_), 256, ATT_SMEM_BYTES>>>();

    gemm_out<<<dim3(D_/128, M_/128), 256, GEMM_SMEM_BYTES>>>(bo, out);
}